// round 6
// baseline (speedup 1.0000x reference)
#include <cuda_runtime.h>
#include <cstdint>

#define BB 8
#define CC 8
#define HH 512
#define WW 512
#define PLANE (HH*WW)                 // 262144
#define PIX   (BB*HH*WW)              // 2097152
#define NEL   (BB*CC*HH*WW)           // 16777216

#define TPB   64                      // threads per block (2 warps)
#define RPT   8                       // rows per thread
#define CPB   (TPB*4)                 // 256 cols per block
#define NBX   (WW/CPB)                // 2
#define NBY   (HH/RPT)                // 64
#define NBLK  (NBX*NBY*BB)            // 1024

__device__ double       g_acc;        // zero-init; reset by last block each run
__device__ unsigned int g_count;      // wraps to 0 via atomicInc

// sigmoid via single-MUFU tanh.approx: sigma(x) = 0.5 + 0.5*tanh(x/2)
__device__ __forceinline__ float sigt(float x) {
    float t;
    asm("tanh.approx.f32 %0, %1;" : "=f"(t) : "f"(0.5f * x));
    return fmaf(0.5f, t, 0.5f);
}
__device__ __forceinline__ float4 ld4(const float* __restrict__ p) {
    return *reinterpret_cast<const float4*>(p);
}
__device__ __forceinline__ float clog(float x) {
    return fmaxf(__logf(x), -100.0f);   // matches jnp.clip(log(x), -100)
}

// col w0-1 of same row/channel: left lane's a[3]; lane-0 fixup LDG
__device__ __forceinline__ float getL(const float a[4], const float* __restrict__ g,
                                      bool ok, int lane) {
    float v = __shfl_up_sync(0xffffffffu, a[3], 1);
    if (lane == 0) v = ok ? sigt(__ldg(g)) : 0.0f;
    return v;
}
// col w0+4: right lane's a[0]; lane-31 fixup LDG
__device__ __forceinline__ float getR(const float a[4], const float* __restrict__ g,
                                      bool ok, int lane) {
    float v = __shfl_down_sync(0xffffffffu, a[0], 1);
    if (lane == 31) v = ok ? sigt(__ldg(g)) : 0.0f;
    return v;
}

// con_target bitmasks (4 px x 8 bits) + target bits packed into one u64
__device__ __forceinline__ unsigned long long build_mask(
        const float* __restrict__ cb, const float* __restrict__ tb) {
    unsigned m0 = 0, m1 = 0, m2 = 0, m3 = 0;
#pragma unroll
    for (int c = 0; c < 8; c++) {
        float4 t = ld4(cb + c * PLANE);
        m0 |= ((unsigned)(t.x > 0.5f)) << c;
        m1 |= ((unsigned)(t.y > 0.5f)) << c;
        m2 |= ((unsigned)(t.z > 0.5f)) << c;
        m3 |= ((unsigned)(t.w > 0.5f)) << c;
    }
    float4 tg = ld4(tb);
    unsigned t4 = (unsigned)(tg.x > 0.5f) | ((unsigned)(tg.y > 0.5f) << 1)
                | ((unsigned)(tg.z > 0.5f) << 2) | ((unsigned)(tg.w > 0.5f) << 3);
    return (unsigned long long)(m0 | (m1 << 8) | (m2 << 16) | (m3 << 24))
         | ((unsigned long long)t4 << 32);
}

// votes + loss terms for one row of a 4-pixel strip.
// Shm: ch5,6,7 sigmoids at row r-1; C: all 8 ch at row r; Sn: ch0,1,2 at row r+1.
__device__ __forceinline__ float row_votes(
    const float Shm[3][4], const float C[8][4], const float Sn[3][4],
    const float* __restrict__ xb, int r, int w0,
    bool wlo, bool whi, int lane, bool hmok, bool hpok,
    unsigned long long mp, int pass)
{
    const float* rm = xb + (r - 1) * WW + w0;
    const float* rc = xb + r * WW + w0;
    const float* rp = xb + (r + 1) * WW + w0;

    float L7 = getL(Shm[2], rm + 7 * PLANE - 1, hmok && !wlo, lane);
    float R5 = getR(Shm[0], rm + 5 * PLANE + 4, hmok && !whi, lane);
    float L4 = getL(C[4],   rc + 4 * PLANE - 1, !wlo,         lane);
    float R3 = getR(C[3],   rc + 3 * PLANE + 4, !whi,         lane);
    float L2 = getL(Sn[2],  rp + 2 * PLANE - 1, hpok && !wlo, lane);
    float R0 = getR(Sn[0],  rp + 0 * PLANE + 4, hpok && !whi, lane);

    float accb = 0.0f, accp = 0.0f;
#pragma unroll
    for (int p = 0; p < 4; p++) {
        float nb[8];
        nb[0] = (p == 0) ? L7 : Shm[2][p == 0 ? 0 : p - 1];   // c7(r-1, w-1)
        nb[1] = Shm[1][p];                                    // c6(r-1, w)
        nb[2] = (p == 3) ? R5 : Shm[0][p == 3 ? 3 : p + 1];   // c5(r-1, w+1)
        nb[3] = (p == 0) ? L4 : C[4][p == 0 ? 0 : p - 1];     // c4(r,   w-1)
        nb[4] = (p == 3) ? R3 : C[3][p == 3 ? 3 : p + 1];     // c3(r,   w+1)
        nb[5] = (p == 0) ? L2 : Sn[2][p == 0 ? 0 : p - 1];    // c2(r+1, w-1)
        nb[6] = Sn[1][p];                                     // c1(r+1, w)
        nb[7] = (p == 3) ? R0 : Sn[0][p == 3 ? 3 : p + 1];    // c0(r+1, w+1)

        unsigned m = (unsigned)(mp >> (8 * p)) & 0xFFu;
        bool T = (mp >> (32 + p)) & 1ull;

        float pA0 = 1.f, pA1 = 1.f, pB0 = 1.f, pB1 = 1.f;
        float glo = 0.f, mn = 1e30f;
        int npen = 0;
#pragma unroll
        for (int k = 0; k < 8; k++) {
            float s = C[k][p];
            float v = s * nb[k];
            glo += v;
            mn = fminf(mn, v);
            bool t = (m >> k) & 1u;
            float A = t ? v : 1.0f - v;
            if (A == 0.0f) { npen++; A = 1.0f; }   // padded border: exact -100 later
            float Bv = t ? s : 1.0f - s;
            if (k < 4) { pA0 *= A; pB0 *= Bv; }
            else       { pA1 *= A; pB1 *= Bv; }
        }
        float bic = __logf(pA0) + __logf(pA1) - 100.0f * (float)npen;
        float co  = __logf(pB0) + __logf(pB1);
        accb += 0.2f * bic + 0.8f * co;

        float g = glo * 0.125f;
        float x;
        if (pass == 0) {
            x = T ? g : 1.0f - g;                        // bce_loss1
        } else {
            bool edge = (m != 0u) && (m != 255u);
            float de  = edge ? (1.0f - mn) : g;          // decouple map
            x = T ? de : 1.0f - de;
        }
        accp += clog(x);
    }
    return accb * (1.0f / (float)NEL) + accp * (1.0f / (float)PIX);
}

__global__ void __launch_bounds__(TPB, 10)
bicon_loss_kernel(const float* __restrict__ atts,
                  const float* __restrict__ dets,
                  const float* __restrict__ target,
                  const float* __restrict__ con,
                  float* __restrict__ out)
{
    __shared__ unsigned long long mk[RPT * TPB];   // 4 KB per-thread mask cache
    __shared__ float wsum[TPB / 32];

    const int tid  = threadIdx.x;
    const int lane = tid & 31;
    const int bid  = blockIdx.x;
    const int cpart = bid & (NBX - 1);
    const int band  = (bid / NBX) & (NBY - 1);
    const int b     = bid / (NBX * NBY);
    const int w0 = cpart * CPB + tid * 4;
    const int r0 = band * RPT;
    const bool wlo = (w0 == 0), whi = (w0 + 4 == WW);

    const size_t bst = (size_t)CC * PLANE;
    const float* cb0 = con + (size_t)b * bst;
    const float* tb0 = target + (size_t)b * PLANE;

    float contrib = 0.0f;

#pragma unroll 1
    for (int pass = 0; pass < 2; pass++) {
        const float* xb = (pass ? dets : atts) + (size_t)b * bst;

        // prologue: row r0-1 channels 5..7; row r0 all 8
        float Shm[3][4];
        if (r0 > 0) {
            const float* pm = xb + (r0 - 1) * WW + w0;
#pragma unroll
            for (int j = 0; j < 3; j++) {
                float4 x = ld4(pm + (5 + j) * PLANE);
                Shm[j][0] = sigt(x.x); Shm[j][1] = sigt(x.y);
                Shm[j][2] = sigt(x.z); Shm[j][3] = sigt(x.w);
            }
        } else {
#pragma unroll
            for (int j = 0; j < 3; j++)
#pragma unroll
                for (int p = 0; p < 4; p++) Shm[j][p] = 0.0f;
        }
        float C[8][4];
        {
            const float* pc = xb + r0 * WW + w0;
#pragma unroll
            for (int c = 0; c < 8; c++) {
                float4 x = ld4(pc + c * PLANE);
                C[c][0] = sigt(x.x); C[c][1] = sigt(x.y);
                C[c][2] = sigt(x.z); C[c][3] = sigt(x.w);
            }
        }

#pragma unroll 1
        for (int i = 0; i < RPT; i++) {
            const int r = r0 + i;
            unsigned long long mp;
            if (pass == 0) {
                mp = build_mask(cb0 + r * WW + w0, tb0 + r * WW + w0);
                mk[i * TPB + tid] = mp;          // private slot, no barrier needed
            } else {
                mp = mk[i * TPB + tid];
            }

            const bool hpok = (r + 1 < HH);
            float Sn[3][4];                      // only ch0..2 of row r+1 pre-vote
            if (hpok) {
                const float* pp = xb + (r + 1) * WW + w0;
#pragma unroll
                for (int c = 0; c < 3; c++) {
                    float4 x = ld4(pp + c * PLANE);
                    Sn[c][0] = sigt(x.x); Sn[c][1] = sigt(x.y);
                    Sn[c][2] = sigt(x.z); Sn[c][3] = sigt(x.w);
                }
            } else {
#pragma unroll
                for (int c = 0; c < 3; c++)
#pragma unroll
                    for (int p = 0; p < 4; p++) Sn[c][p] = 0.0f;
            }

            contrib += row_votes(Shm, C, Sn, xb, r, w0, wlo, whi, lane,
                                 r > 0, hpok, mp, pass);

            if (i < RPT - 1) {   // roll state down one row
#pragma unroll
                for (int j = 0; j < 3; j++)
#pragma unroll
                    for (int p = 0; p < 4; p++) Shm[j][p] = C[5 + j][p];
#pragma unroll
                for (int c = 0; c < 3; c++)
#pragma unroll
                    for (int p = 0; p < 4; p++) C[c][p] = Sn[c][p];
                const float* pn = xb + (r + 1) * WW + w0;
#pragma unroll
                for (int c = 3; c < 8; c++) {
                    float4 x = ld4(pn + c * PLANE);
                    C[c][0] = sigt(x.x); C[c][1] = sigt(x.y);
                    C[c][2] = sigt(x.z); C[c][3] = sigt(x.w);
                }
            }
        }
    }

    // block reduction: warp shfl -> smem -> one double atomic per block
#pragma unroll
    for (int o = 16; o > 0; o >>= 1)
        contrib += __shfl_down_sync(0xFFFFFFFFu, contrib, o);
    if (lane == 0) wsum[tid >> 5] = contrib;
    __syncthreads();

    if (tid == 0) {
        float s = 0.0f;
#pragma unroll
        for (int i = 0; i < TPB / 32; i++) s += wsum[i];
        atomicAdd(&g_acc, (double)s);
        __threadfence();
        unsigned old = atomicInc(&g_count, NBLK - 1u);   // wraps to 0 on last
        if (old == NBLK - 1u) {
            unsigned long long raw =
                atomicExch((unsigned long long*)&g_acc, 0ULL);
            out[0] = -(float)__longlong_as_double(raw);
        }
    }
}

extern "C" void kernel_launch(void* const* d_in, const int* in_sizes, int n_in,
                              void* d_out, int out_size) {
    const float* atts   = (const float*)d_in[0];
    const float* dets   = (const float*)d_in[1];
    const float* target = (const float*)d_in[2];
    const float* con    = (const float*)d_in[3];
    float* out = (float*)d_out;

    bicon_loss_kernel<<<NBLK, TPB>>>(atts, dets, target, con, out);
}

// round 7
// speedup vs baseline: 1.1074x; 1.1074x over previous
#include <cuda_runtime.h>
#include <cstdint>

#define BB 8
#define CC 8
#define HH 512
#define WW 512
#define PLANE (HH*WW)                 // 262144
#define PIX   (BB*HH*WW)              // 2097152
#define NEL   (BB*CC*HH*WW)           // 16777216

#define TPB   64                      // threads per block (2 warps)
#define RPT   4                       // rows per thread
#define CPB   (TPB*4)                 // 256 cols per block
#define NBX   (WW/CPB)                // 2
#define NBY   (HH/RPT)                // 128
#define NBLK  (NBX*NBY*BB)            // 2048

__device__ double       g_acc;        // zero-init; reset by last block each run
__device__ unsigned int g_count;      // wraps to 0 via atomicInc

// sigmoid via single-MUFU tanh.approx: sigma(x) = 0.5 + 0.5*tanh(x/2)
__device__ __forceinline__ float sigt(float x) {
    float t;
    asm("tanh.approx.f32 %0, %1;" : "=f"(t) : "f"(0.5f * x));
    return fmaf(0.5f, t, 0.5f);
}
__device__ __forceinline__ float4 ld4(const float* __restrict__ p) {
    return *reinterpret_cast<const float4*>(p);
}
__device__ __forceinline__ float clog(float x) {
    return fmaxf(__logf(x), -100.0f);   // matches jnp.clip(log(x), -100)
}

// col w0-1 of same row/channel: left lane's a[3]; lane-0 fixup LDG
__device__ __forceinline__ float getL(const float a[4], const float* __restrict__ g,
                                      bool ok, int lane) {
    float v = __shfl_up_sync(0xffffffffu, a[3], 1);
    if (lane == 0) v = ok ? sigt(__ldg(g)) : 0.0f;
    return v;
}
// col w0+4: right lane's a[0]; lane-31 fixup LDG
__device__ __forceinline__ float getR(const float a[4], const float* __restrict__ g,
                                      bool ok, int lane) {
    float v = __shfl_down_sync(0xffffffffu, a[0], 1);
    if (lane == 31) v = ok ? sigt(__ldg(g)) : 0.0f;
    return v;
}

// con_target bitmasks (4 px x 8 bits) + target bits packed into one u64
__device__ __forceinline__ unsigned long long build_mask(
        const float* __restrict__ cb, const float* __restrict__ tb) {
    unsigned m0 = 0, m1 = 0, m2 = 0, m3 = 0;
#pragma unroll
    for (int c = 0; c < 8; c++) {
        float4 t = ld4(cb + c * PLANE);
        m0 |= ((unsigned)(t.x > 0.5f)) << c;
        m1 |= ((unsigned)(t.y > 0.5f)) << c;
        m2 |= ((unsigned)(t.z > 0.5f)) << c;
        m3 |= ((unsigned)(t.w > 0.5f)) << c;
    }
    float4 tg = ld4(tb);
    unsigned t4 = (unsigned)(tg.x > 0.5f) | ((unsigned)(tg.y > 0.5f) << 1)
                | ((unsigned)(tg.z > 0.5f) << 2) | ((unsigned)(tg.w > 0.5f) << 3);
    return (unsigned long long)(m0 | (m1 << 8) | (m2 << 16) | (m3 << 24))
         | ((unsigned long long)t4 << 32);
}

// votes + loss terms for one row of a 4-pixel strip.
// Shm: ch5,6,7 sigmoids at row r-1; C: all 8 ch at row r; Sn: ch0,1,2 at row r+1.
// px points at (row r, col w0); rm/rp are constant offsets folded into LDG.
__device__ __forceinline__ float row_votes(
    const float Shm[3][4], const float C[8][4], const float Sn[3][4],
    const float* __restrict__ px,
    bool wlo, bool whi, int lane, bool hmok, bool hpok,
    unsigned long long mp, int pass)
{
    float L7 = getL(Shm[2], px - WW + 7 * PLANE - 1, hmok && !wlo, lane);
    float R5 = getR(Shm[0], px - WW + 5 * PLANE + 4, hmok && !whi, lane);
    float L4 = getL(C[4],   px      + 4 * PLANE - 1, !wlo,         lane);
    float R3 = getR(C[3],   px      + 3 * PLANE + 4, !whi,         lane);
    float L2 = getL(Sn[2],  px + WW + 2 * PLANE - 1, hpok && !wlo, lane);
    float R0 = getR(Sn[0],  px + WW + 0 * PLANE + 4, hpok && !whi, lane);

    float accb = 0.0f, accp = 0.0f;
#pragma unroll
    for (int p = 0; p < 4; p++) {
        float nb[8];
        nb[0] = (p == 0) ? L7 : Shm[2][p == 0 ? 0 : p - 1];   // c7(r-1, w-1)
        nb[1] = Shm[1][p];                                    // c6(r-1, w)
        nb[2] = (p == 3) ? R5 : Shm[0][p == 3 ? 3 : p + 1];   // c5(r-1, w+1)
        nb[3] = (p == 0) ? L4 : C[4][p == 0 ? 0 : p - 1];     // c4(r,   w-1)
        nb[4] = (p == 3) ? R3 : C[3][p == 3 ? 3 : p + 1];     // c3(r,   w+1)
        nb[5] = (p == 0) ? L2 : Sn[2][p == 0 ? 0 : p - 1];    // c2(r+1, w-1)
        nb[6] = Sn[1][p];                                     // c1(r+1, w)
        nb[7] = (p == 3) ? R0 : Sn[0][p == 3 ? 3 : p + 1];    // c0(r+1, w+1)

        unsigned m = (unsigned)(mp >> (8 * p)) & 0xFFu;
        bool T = (mp >> (32 + p)) & 1ull;

        float pA0 = 1.f, pA1 = 1.f, pB0 = 1.f, pB1 = 1.f;
        float glo = 0.f, mn = 1e30f;
        int npen = 0;
#pragma unroll
        for (int k = 0; k < 8; k++) {
            float s = C[k][p];
            float v = s * nb[k];
            glo += v;
            mn = fminf(mn, v);
            bool t = (m >> k) & 1u;
            float A = t ? v : 1.0f - v;
            if (A == 0.0f) { npen++; A = 1.0f; }   // padded border: exact -100 later
            float Bv = t ? s : 1.0f - s;
            if (k < 4) { pA0 *= A; pB0 *= Bv; }
            else       { pA1 *= A; pB1 *= Bv; }
        }
        float bic = __logf(pA0) + __logf(pA1) - 100.0f * (float)npen;
        float co  = __logf(pB0) + __logf(pB1);
        accb += 0.2f * bic + 0.8f * co;

        float g = glo * 0.125f;
        float x;
        if (pass == 0) {
            x = T ? g : 1.0f - g;                        // bce_loss1
        } else {
            bool edge = (m != 0u) && (m != 255u);
            float de  = edge ? (1.0f - mn) : g;          // decouple map
            x = T ? de : 1.0f - de;
        }
        accp += clog(x);
    }
    return accb * (1.0f / (float)NEL) + accp * (1.0f / (float)PIX);
}

__global__ void __launch_bounds__(TPB, 8)
bicon_loss_kernel(const float* __restrict__ atts,
                  const float* __restrict__ dets,
                  const float* __restrict__ target,
                  const float* __restrict__ con,
                  float* __restrict__ out)
{
    __shared__ unsigned long long mk[RPT * TPB];   // 2 KB per-thread mask cache
    __shared__ float wsum[TPB / 32];

    const int tid  = threadIdx.x;
    const int lane = tid & 31;
    const int bid  = blockIdx.x;
    const int cpart = bid & (NBX - 1);
    const int band  = (bid / NBX) & (NBY - 1);
    const int b     = bid / (NBX * NBY);
    const int w0 = cpart * CPB + tid * 4;
    const int r0 = band * RPT;
    const bool wlo = (w0 == 0), whi = (w0 + 4 == WW);

    const size_t bst  = (size_t)CC * PLANE;
    const size_t soff = (size_t)r0 * WW + w0;   // strip offset within batch image

    float contrib = 0.0f;

#pragma unroll
    for (int pass = 0; pass < 2; pass++) {
        const float* px = (pass ? dets : atts) + (size_t)b * bst + soff;

        // prologue: row r0-1 channels 5..7; row r0 all 8 (immediate offsets)
        float Shm[3][4];
        if (r0 > 0) {
#pragma unroll
            for (int j = 0; j < 3; j++) {
                float4 x = ld4(px - WW + (5 + j) * PLANE);
                Shm[j][0] = sigt(x.x); Shm[j][1] = sigt(x.y);
                Shm[j][2] = sigt(x.z); Shm[j][3] = sigt(x.w);
            }
        } else {
#pragma unroll
            for (int j = 0; j < 3; j++)
#pragma unroll
                for (int p = 0; p < 4; p++) Shm[j][p] = 0.0f;
        }
        float C[8][4];
#pragma unroll
        for (int c = 0; c < 8; c++) {
            float4 x = ld4(px + c * PLANE);
            C[c][0] = sigt(x.x); C[c][1] = sigt(x.y);
            C[c][2] = sigt(x.z); C[c][3] = sigt(x.w);
        }

        const float* cpx = con + (size_t)b * bst + soff;       // rolling con ptr
        const float* tpx = target + (size_t)b * PLANE + soff;  // rolling target ptr

#pragma unroll 1
        for (int i = 0; i < RPT - 1; i++) {
            const int r = r0 + i;
            unsigned long long mp;
            if (pass == 0) {
                mp = build_mask(cpx, tpx);
                mk[i * TPB + tid] = mp;          // private slot, no barrier needed
            } else {
                mp = mk[i * TPB + tid];
            }
            // full next-row prefetch (8 independent LDG.128 in flight)
            float N[8][4];
#pragma unroll
            for (int c = 0; c < 8; c++) {
                float4 x = ld4(px + WW + c * PLANE);
                N[c][0] = sigt(x.x); N[c][1] = sigt(x.y);
                N[c][2] = sigt(x.z); N[c][3] = sigt(x.w);
            }

            contrib += row_votes(Shm, C, N, px, wlo, whi, lane,
                                 r > 0, true, mp, pass);
            // roll
#pragma unroll
            for (int j = 0; j < 3; j++)
#pragma unroll
                for (int p = 0; p < 4; p++) Shm[j][p] = C[5 + j][p];
#pragma unroll
            for (int c = 0; c < 8; c++)
#pragma unroll
                for (int p = 0; p < 4; p++) C[c][p] = N[c][p];
            px  += WW;
            cpx += WW;
            tpx += WW;
        }
        {   // last row of band: next row needs only channels 0..2
            const int r = r0 + RPT - 1;
            unsigned long long mp;
            if (pass == 0) {
                mp = build_mask(cpx, tpx);
                mk[(RPT - 1) * TPB + tid] = mp;
            } else {
                mp = mk[(RPT - 1) * TPB + tid];
            }
            const bool hpok = (r + 1 < HH);
            float Sn[3][4];
            if (hpok) {
#pragma unroll
                for (int c = 0; c < 3; c++) {
                    float4 x = ld4(px + WW + c * PLANE);
                    Sn[c][0] = sigt(x.x); Sn[c][1] = sigt(x.y);
                    Sn[c][2] = sigt(x.z); Sn[c][3] = sigt(x.w);
                }
            } else {
#pragma unroll
                for (int c = 0; c < 3; c++)
#pragma unroll
                    for (int p = 0; p < 4; p++) Sn[c][p] = 0.0f;
            }
            contrib += row_votes(Shm, C, Sn, px, wlo, whi, lane,
                                 true, hpok, mp, pass);
        }
    }

    // block reduction: warp shfl -> smem -> one double atomic per block
#pragma unroll
    for (int o = 16; o > 0; o >>= 1)
        contrib += __shfl_down_sync(0xFFFFFFFFu, contrib, o);
    if (lane == 0) wsum[tid >> 5] = contrib;
    __syncthreads();

    if (tid == 0) {
        float s = 0.0f;
#pragma unroll
        for (int i = 0; i < TPB / 32; i++) s += wsum[i];
        atomicAdd(&g_acc, (double)s);
        __threadfence();
        unsigned old = atomicInc(&g_count, NBLK - 1u);   // wraps to 0 on last
        if (old == NBLK - 1u) {
            unsigned long long raw =
                atomicExch((unsigned long long*)&g_acc, 0ULL);
            out[0] = -(float)__longlong_as_double(raw);
        }
    }
}

extern "C" void kernel_launch(void* const* d_in, const int* in_sizes, int n_in,
                              void* d_out, int out_size) {
    const float* atts   = (const float*)d_in[0];
    const float* dets   = (const float*)d_in[1];
    const float* target = (const float*)d_in[2];
    const float* con    = (const float*)d_in[3];
    float* out = (float*)d_out;

    bicon_loss_kernel<<<NBLK, TPB>>>(atts, dets, target, con, out);
}